// round 13
// baseline (speedup 1.0000x reference)
#include <cuda_runtime.h>

#define NN   50000
#define EE   600000
#define EP   650000      // EE + NN self loops
#define FEAT 32
#define ACTD 8
#define HDIM 128
#define NEG  0.2f
#define LEPS 1e-5f
#define GROWS 48         // rows per k_gemm_gat block

typedef unsigned long long u64t;

// ---------------- device scratch (no allocations allowed) ----------------
__device__ float g_h    [NN * HDIM];
__device__ float g_xp   [NN * HDIM];
__device__ float g_ssrc [NN * 4];
__device__ float g_sdst [NN * 4];
__device__ int   g_cnt  [NN];
__device__ int   g_off  [NN + 1];
__device__ int   g_cur  [NN];
__device__ int   g_srcs [EP];
__device__ float g_gsum [HDIM];

__device__ __forceinline__ float lrelu(float a) { return a > 0.f ? a : NEG * a; }
__device__ __forceinline__ float wredsum(float v) {
    #pragma unroll
    for (int o = 16; o > 0; o >>= 1) v += __shfl_xor_sync(0xffffffffu, v, o);
    return v;
}
__device__ __forceinline__ u64t fma2(u64t a, u64t b, u64t c) {
    u64t d;
    asm("fma.rn.f32x2 %0, %1, %2, %3;" : "=l"(d) : "l"(a), "l"(b), "l"(c));
    return d;
}
__device__ __forceinline__ float2 unpk(u64t v) {
    float2 r;
    asm("mov.b64 {%0, %1}, %2;" : "=f"(r.x), "=f"(r.y) : "l"(v));
    return r;
}

// ---------------- CSR build ----------------
__global__ void k_zero() {
    int i = blockIdx.x * blockDim.x + threadIdx.x;
    if (i < NN)   g_cnt[i]  = 0;
    if (i < HDIM) g_gsum[i] = 0.f;
}

__global__ void k_hist(const int* __restrict__ ei) {
    int e = blockIdx.x * blockDim.x + threadIdx.x;
    if (e >= EP) return;
    int d = (e < EE) ? ei[EE + e] : (e - EE);
    atomicAdd(&g_cnt[d], 1);
}

__global__ void k_scan() {
    __shared__ int ps[1024];
    int t = threadIdx.x;
    const int CH = (NN + 1023) / 1024;     // 49
    int s0 = t * CH;
    int s1 = min(s0 + CH, NN);
    int s = 0;
    for (int i = s0; i < s1; i++) s += g_cnt[i];
    ps[t] = s;
    __syncthreads();
    #pragma unroll
    for (int d = 1; d < 1024; d <<= 1) {
        int add = (t >= d) ? ps[t - d] : 0;
        __syncthreads();
        ps[t] += add;
        __syncthreads();
    }
    int run = t ? ps[t - 1] : 0;
    for (int i = s0; i < s1; i++) {
        g_off[i] = run;
        g_cur[i] = run;
        run += g_cnt[i];
    }
    if (t == 1023) g_off[NN] = ps[1023];
}

__global__ void k_scatter(const int* __restrict__ ei) {
    int e = blockIdx.x * blockDim.x + threadIdx.x;
    if (e >= EP) return;
    int s, d;
    if (e < EE) { s = ei[e]; d = ei[EE + e]; }
    else        { s = e - EE; d = s; }
    int p = atomicAdd(&g_cur[d], 1);
    g_srcs[p] = s;
}

// ---------------- encoder (f32x2): h = relu(LN(concat(x,act) @ W0 + b0)) --------------
__global__ void __launch_bounds__(256) k_enc(
    const float* __restrict__ x, const float* __restrict__ act,
    const float* __restrict__ W0, const float* __restrict__ b0,
    const float* __restrict__ lg, const float* __restrict__ lb)
{
    __shared__ float Wsm[20 * 256];   // k-pair interleaved: (k,c) -> (k/2)*256 + c*2 + (k&1)
    __shared__ float Rsm[32 * 40];
    int tid = threadIdx.x;
    for (int i = tid; i < 40 * HDIM; i += 256) {
        int k = i >> 7, c = i & 127;
        Wsm[(k >> 1) * 256 + c * 2 + (k & 1)] = W0[i];
    }
    int row0 = blockIdx.x * 32;
    for (int i = tid; i < 32 * 40; i += 256) {
        int r = i / 40, c = i - r * 40;
        int row = row0 + r;
        float v = 0.f;
        if (row < NN) v = (c < FEAT) ? x[row * FEAT + c] : act[row * ACTD + (c - FEAT)];
        Rsm[i] = v;
    }
    __syncthreads();
    int l = tid & 31, w4 = (tid >> 5) * 4;
    u64t acc[4][4] = {};
    #pragma unroll 4
    for (int kk = 0; kk < 20; kk++) {
        const u64t* wrow = (const u64t*)(Wsm + kk * 256);
        u64t w0 = wrow[l], w1 = wrow[l + 32], w2 = wrow[l + 64], w3 = wrow[l + 96];
        #pragma unroll
        for (int i = 0; i < 4; i++) {
            u64t h = *(const u64t*)(Rsm + (w4 + i) * 40 + kk * 2);
            acc[i][0] = fma2(h, w0, acc[i][0]);
            acc[i][1] = fma2(h, w1, acc[i][1]);
            acc[i][2] = fma2(h, w2, acc[i][2]);
            acc[i][3] = fma2(h, w3, acc[i][3]);
        }
    }
    float bb0 = b0[l], bb1 = b0[l + 32], bb2 = b0[l + 64], bb3 = b0[l + 96];
    float gg0 = lg[l], gg1 = lg[l + 32], gg2 = lg[l + 64], gg3 = lg[l + 96];
    float be0 = lb[l], be1 = lb[l + 32], be2 = lb[l + 64], be3 = lb[l + 96];
    #pragma unroll
    for (int i = 0; i < 4; i++) {
        int row = row0 + w4 + i;
        float2 p0 = unpk(acc[i][0]), p1 = unpk(acc[i][1]);
        float2 p2 = unpk(acc[i][2]), p3 = unpk(acc[i][3]);
        float v0 = p0.x + p0.y + bb0, v1 = p1.x + p1.y + bb1;
        float v2 = p2.x + p2.y + bb2, v3 = p3.x + p3.y + bb3;
        float sum = wredsum(v0 + v1 + v2 + v3);
        float sq  = wredsum(v0 * v0 + v1 * v1 + v2 * v2 + v3 * v3);
        float mu  = sum * (1.f / HDIM);
        float var = sq * (1.f / HDIM) - mu * mu;
        float rs  = rsqrtf(var + LEPS);
        if (row < NN) {
            int o = row * HDIM + l;
            g_h[o]      = fmaxf((v0 - mu) * rs * gg0 + be0, 0.f);
            g_h[o + 32] = fmaxf((v1 - mu) * rs * gg1 + be1, 0.f);
            g_h[o + 64] = fmaxf((v2 - mu) * rs * gg2 + be2, 0.f);
            g_h[o + 96] = fmaxf((v3 - mu) * rs * gg3 + be3, 0.f);
        }
    }
}

// ---------------- GAT linear (f32x2 + LDS.128 quad-k): 48 rows x 64 cols per block ----
// W quad-interleaved: (k, c0+cc) -> Wsm[(k/4)*256 + cc*4 + (k&3)] so one LDS.128 per
// lane covers 4 k-steps of one column. Hsm rows have k contiguous -> LDS.128 broadcast.
// Per 4 k-steps: 8 LDS.128 feed 24 fma2 (was 16 LDS.64 per 24 fma2) -> crossbar halved.
__global__ void __launch_bounds__(256) k_gemm_gat(
    const float* __restrict__ W,
    const float* __restrict__ asrc, const float* __restrict__ adst)
{
    extern __shared__ float sm[];
    float* Wsm = sm;                    // 32 kq-rows * 256 floats = 32KB
    float* Hsm = sm + 64 * 128;         // GROWS * 128 = 24KB
    int tid = threadIdx.x;
    int bx = blockIdx.x >> 1, chalf = blockIdx.x & 1;
    int c0 = chalf * 64;
    for (int i = tid; i < HDIM * 64; i += 256) {
        int k = i >> 6, cc = i & 63;
        Wsm[(k >> 2) * 256 + cc * 4 + (k & 3)] = W[k * HDIM + c0 + cc];
    }
    int row0 = bx * GROWS;
    for (int i = tid; i < GROWS * HDIM; i += 256) {
        int r = i >> 7, c = i & 127;
        int row = row0 + r;
        Hsm[i] = (row < NN) ? g_h[row * HDIM + c] : 0.f;
    }
    __syncthreads();
    int l = tid & 31, w6 = (tid >> 5) * 6;
    u64t acc[6][2] = {};
    #pragma unroll 4
    for (int kq = 0; kq < 32; kq++) {
        const longlong2* wr = (const longlong2*)(Wsm + kq * 256);
        longlong2 wA = wr[l], wB = wr[l + 32];
        #pragma unroll
        for (int i = 0; i < 6; i++) {
            longlong2 hv = *(const longlong2*)(Hsm + (w6 + i) * HDIM + kq * 4);
            acc[i][0] = fma2((u64t)hv.x, (u64t)wA.x, acc[i][0]);
            acc[i][0] = fma2((u64t)hv.y, (u64t)wA.y, acc[i][0]);
            acc[i][1] = fma2((u64t)hv.x, (u64t)wB.x, acc[i][1]);
            acc[i][1] = fma2((u64t)hv.y, (u64t)wB.y, acc[i][1]);
        }
    }
    float as0 = asrc[c0 + l], as1 = asrc[c0 + 32 + l];
    float ad0 = adst[c0 + l], ad1 = adst[c0 + 32 + l];
    #pragma unroll
    for (int i = 0; i < 6; i++) {
        int row = row0 + w6 + i;
        float2 u0 = unpk(acc[i][0]), u1 = unpk(acc[i][1]);
        float v0 = u0.x + u0.y, v1 = u1.x + u1.y;
        float p0 = wredsum(v0 * as0);   // head chalf*2 + 0
        float p1 = wredsum(v1 * as1);   // head chalf*2 + 1
        float q0 = wredsum(v0 * ad0);
        float q1 = wredsum(v1 * ad1);
        if (row < NN) {
            if (l == 0) {
                g_ssrc[row * 4 + chalf * 2 + 0] = p0;
                g_ssrc[row * 4 + chalf * 2 + 1] = p1;
                g_sdst[row * 4 + chalf * 2 + 0] = q0;
                g_sdst[row * 4 + chalf * 2 + 1] = q1;
            }
            int o = row * HDIM + c0 + l;
            g_xp[o]      = v0;
            g_xp[o + 32] = v1;
        }
    }
}

// ---------------- single-pass attention + aggregate + LN + relu + residual ------------
__global__ void __launch_bounds__(256) k_attn(
    const float* __restrict__ bias,
    const float* __restrict__ lg, const float* __restrict__ lb)
{
    __shared__ float sw[8][128];
    int warp = threadIdx.x >> 5, lane = threadIdx.x & 31;
    int node = blockIdx.x * 8 + warp;      // grid = NN/8 exactly
    int beg = g_off[node], end = g_off[node + 1];
    const float4 sd = *(const float4*)(g_sdst + node * 4);

    int head = lane >> 3;
    int colb = lane * 4;
    float den0 = 0.f, den1 = 0.f, den2 = 0.f, den3 = 0.f;
    float4 acc = make_float4(0.f, 0.f, 0.f, 0.f);

    for (int base = beg; base < end; base += 32) {
        int e = base + lane;
        int s = 0;
        float a0 = 0.f, a1 = 0.f, a2 = 0.f, a3 = 0.f;
        if (e < end) {
            s = g_srcs[e];
            float4 sv = *(const float4*)(g_ssrc + s * 4);
            a0 = __expf(lrelu(sv.x + sd.x));
            a1 = __expf(lrelu(sv.y + sd.y));
            a2 = __expf(lrelu(sv.z + sd.z));
            a3 = __expf(lrelu(sv.w + sd.w));
        }
        den0 += a0; den1 += a1; den2 += a2; den3 += a3;
        __syncwarp();
        float* swp = sw[warp] + lane * 4;
        swp[0] = a0; swp[1] = a1; swp[2] = a2; swp[3] = a3;
        __syncwarp();
        int cnt4 = (min(32, end - base) + 3) & ~3;
        for (int j = 0; j < cnt4; j += 4) {
            int   sj[4];
            float wv[4];
            #pragma unroll
            for (int u = 0; u < 4; u++) {
                sj[u] = __shfl_sync(0xffffffffu, s, j + u);
                wv[u] = sw[warp][(j + u) * 4 + head];
            }
            #pragma unroll
            for (int u = 0; u < 4; u++) {
                float4 xv = *(const float4*)(g_xp + (size_t)sj[u] * HDIM + colb);
                acc.x = fmaf(wv[u], xv.x, acc.x);
                acc.y = fmaf(wv[u], xv.y, acc.y);
                acc.z = fmaf(wv[u], xv.z, acc.z);
                acc.w = fmaf(wv[u], xv.w, acc.w);
            }
        }
    }

    den0 = wredsum(den0); den1 = wredsum(den1);
    den2 = wredsum(den2); den3 = wredsum(den3);
    float dh = (head == 0) ? den0 : (head == 1) ? den1 : (head == 2) ? den2 : den3;
    float inv = 1.f / dh;
    acc.x *= inv; acc.y *= inv; acc.z *= inv; acc.w *= inv;

    // bias + LayerNorm + relu + residual, fully in-warp
    float4 bb = *(const float4*)(bias + colb);
    acc.x += bb.x; acc.y += bb.y; acc.z += bb.z; acc.w += bb.w;
    float sum = wredsum(acc.x + acc.y + acc.z + acc.w);
    float sq  = wredsum(acc.x * acc.x + acc.y * acc.y + acc.z * acc.z + acc.w * acc.w);
    float mu  = sum * (1.f / 128.f);
    float var = sq * (1.f / 128.f) - mu * mu;
    float rs  = rsqrtf(var + LEPS);
    float4 gg = *(const float4*)(lg + colb);
    float4 be = *(const float4*)(lb + colb);
    float4 hv = *(float4*)(g_h + (size_t)node * HDIM + colb);
    hv.x += fmaxf((acc.x - mu) * rs * gg.x + be.x, 0.f);
    hv.y += fmaxf((acc.y - mu) * rs * gg.y + be.y, 0.f);
    hv.z += fmaxf((acc.z - mu) * rs * gg.z + be.z, 0.f);
    hv.w += fmaxf((acc.w - mu) * rs * gg.w + be.w, 0.f);
    *(float4*)(g_h + (size_t)node * HDIM + colb) = hv;
}

// ---------------- dynamics head (f32x2 + LDS.128 quad-k) + fused mean-pool ------------
__global__ void __launch_bounds__(256) k_dyn(
    const float* __restrict__ x,
    const float* __restrict__ W1, const float* __restrict__ b1,
    const float* __restrict__ W2, const float* __restrict__ b2,
    float* __restrict__ out)
{
    extern __shared__ float sm[];
    float* W1sm = sm;            // 16384 (quad-k interleaved: (k/4)*512 + c*4 + (k&3))
    float* W2sm = sm + 16384;    // 4096  (quad-k interleaved: (k/4)*128 + c*4 + (k&3))
    float* Rsm  = sm + 20480;    // 32*128
    int tid = threadIdx.x;
    for (int i = tid; i < HDIM * HDIM; i += 256) {
        int k = i >> 7, c = i & 127;
        W1sm[(k >> 2) * 512 + c * 4 + (k & 3)] = W1[i];
    }
    for (int i = tid; i < HDIM * FEAT; i += 256) {
        int k = i >> 5, c = i & 31;
        W2sm[(k >> 2) * 128 + c * 4 + (k & 3)] = W2[i];
    }
    int row0 = blockIdx.x * 32;
    for (int i = tid; i < 32 * HDIM; i += 256) {
        int r = i >> 7, c = i & 127;
        int row = row0 + r;
        Rsm[i] = (row < NN) ? g_h[row * HDIM + c] : 0.f;
    }
    __syncthreads();

    // fused global mean-pool partial (h tile already in smem; zeros past NN harmless)
    {
        int col = tid & 127, rh = tid >> 7;
        float s = 0.f;
        #pragma unroll
        for (int r = rh * 16; r < rh * 16 + 16; r++) s += Rsm[r * HDIM + col];
        atomicAdd(&g_gsum[col], s);
    }

    int l = tid & 31, w4 = (tid >> 5) * 4;
    u64t acc[4][4] = {};
    #pragma unroll 2
    for (int kq = 0; kq < 32; kq++) {
        const longlong2* wr = (const longlong2*)(W1sm + kq * 512);
        longlong2 w0 = wr[l], w1 = wr[l + 32], w2 = wr[l + 64], w3 = wr[l + 96];
        #pragma unroll
        for (int i = 0; i < 4; i++) {
            longlong2 hv = *(const longlong2*)(Rsm + (w4 + i) * HDIM + kq * 4);
            acc[i][0] = fma2((u64t)hv.x, (u64t)w0.x, acc[i][0]);
            acc[i][0] = fma2((u64t)hv.y, (u64t)w0.y, acc[i][0]);
            acc[i][1] = fma2((u64t)hv.x, (u64t)w1.x, acc[i][1]);
            acc[i][1] = fma2((u64t)hv.y, (u64t)w1.y, acc[i][1]);
            acc[i][2] = fma2((u64t)hv.x, (u64t)w2.x, acc[i][2]);
            acc[i][2] = fma2((u64t)hv.y, (u64t)w2.y, acc[i][2]);
            acc[i][3] = fma2((u64t)hv.x, (u64t)w3.x, acc[i][3]);
            acc[i][3] = fma2((u64t)hv.y, (u64t)w3.y, acc[i][3]);
        }
    }
    float bb0 = b1[l], bb1 = b1[l + 32], bb2 = b1[l + 64], bb3 = b1[l + 96];
    __syncthreads();
    #pragma unroll
    for (int i = 0; i < 4; i++) {
        int ro = (w4 + i) * HDIM;
        float2 p0 = unpk(acc[i][0]), p1 = unpk(acc[i][1]);
        float2 p2 = unpk(acc[i][2]), p3 = unpk(acc[i][3]);
        Rsm[ro + l]      = fmaxf(p0.x + p0.y + bb0, 0.f);
        Rsm[ro + l + 32] = fmaxf(p1.x + p1.y + bb1, 0.f);
        Rsm[ro + l + 64] = fmaxf(p2.x + p2.y + bb2, 0.f);
        Rsm[ro + l + 96] = fmaxf(p3.x + p3.y + bb3, 0.f);
    }
    __syncthreads();
    u64t dacc[4] = {};
    #pragma unroll 2
    for (int kq = 0; kq < 32; kq++) {
        longlong2 w = *(const longlong2*)(W2sm + kq * 128 + l * 4);
        #pragma unroll
        for (int i = 0; i < 4; i++) {
            longlong2 hv = *(const longlong2*)(Rsm + (w4 + i) * HDIM + kq * 4);
            dacc[i] = fma2((u64t)hv.x, (u64t)w.x, dacc[i]);
            dacc[i] = fma2((u64t)hv.y, (u64t)w.y, dacc[i]);
        }
    }
    float bv = b2[l];
    #pragma unroll
    for (int i = 0; i < 4; i++) {
        int row = row0 + w4 + i;
        if (row < NN) {
            float2 p = unpk(dacc[i]);
            float dv = p.x + p.y + bv;
            out[row * FEAT + l] = dv;
            out[NN * FEAT + row * FEAT + l] = x[row * FEAT + l] + dv;
        }
    }
}

// ---------------- reward/constraint heads ----------------
__global__ void k_heads(
    const float* __restrict__ Wr1, const float* __restrict__ br1,
    const float* __restrict__ Wr2, const float* __restrict__ br2,
    const float* __restrict__ Wc1, const float* __restrict__ bc1,
    const float* __restrict__ Wc2, const float* __restrict__ bc2,
    float* __restrict__ out)
{
    __shared__ float emb[128];
    __shared__ float t1[64];
    __shared__ float t2[64];
    int t = threadIdx.x;   // 128
    emb[t] = g_gsum[t] * (1.f / NN);
    __syncthreads();
    if (t < 64) {
        float a = br1[t], c = bc1[t];
        #pragma unroll 4
        for (int k = 0; k < 128; k++) {
            a = fmaf(emb[k], Wr1[k * 64 + t], a);
            c = fmaf(emb[k], Wc1[k * 64 + t], c);
        }
        t1[t] = fmaxf(a, 0.f);
        t2[t] = fmaxf(c, 0.f);
    }
    __syncthreads();
    if (t == 0) {
        float r = br2[0], c = bc2[0];
        for (int k = 0; k < 64; k++) {
            r = fmaf(t1[k], Wr2[k], r);
            c = fmaf(t2[k], Wc2[k], c);
        }
        out[2 * NN * FEAT]     = r;
        out[2 * NN * FEAT + 1] = 1.f / (1.f + expf(-c));
    }
}

// ---------------- launch (single stream — graph-capture safe) ----------------
extern "C" void kernel_launch(void* const* d_in, const int* in_sizes, int n_in,
                              void* d_out, int out_size)
{
    const float* x    = (const float*)d_in[0];
    const float* act  = (const float*)d_in[1];
    const int*   ei   = (const int*)  d_in[2];
    const float* W0   = (const float*)d_in[3];
    const float* b0   = (const float*)d_in[4];
    const float* ln0g = (const float*)d_in[5];
    const float* ln0b = (const float*)d_in[6];
    const float* Wg   = (const float*)d_in[7];
    const float* asrc = (const float*)d_in[8];
    const float* adst = (const float*)d_in[9];
    const float* bg   = (const float*)d_in[10];
    const float* lngg = (const float*)d_in[11];
    const float* lngb = (const float*)d_in[12];
    const float* Wd1  = (const float*)d_in[13];
    const float* bd1  = (const float*)d_in[14];
    const float* Wd2  = (const float*)d_in[15];
    const float* bd2  = (const float*)d_in[16];
    const float* Wr1  = (const float*)d_in[17];
    const float* br1  = (const float*)d_in[18];
    const float* Wr2  = (const float*)d_in[19];
    const float* br2  = (const float*)d_in[20];
    const float* Wc1  = (const float*)d_in[21];
    const float* bc1  = (const float*)d_in[22];
    const float* Wc2  = (const float*)d_in[23];
    const float* bc2  = (const float*)d_in[24];
    float* out = (float*)d_out;

    cudaFuncSetAttribute(k_gemm_gat, cudaFuncAttributeMaxDynamicSharedMemorySize, 57344);
    cudaFuncSetAttribute(k_dyn,      cudaFuncAttributeMaxDynamicSharedMemorySize, 98304);

    const int GEMM_GRID = ((NN + GROWS - 1) / GROWS) * 2;   // split-N: 2 col-halves

    // Interleave CSR build with encoder/layer-0 GEMM (sequentially correct on one
    // stream; keeps k_gemm_gat in the ncu capture slot for visibility).
    k_zero   <<<(NN + 255) / 256, 256>>>();
    k_enc    <<<(NN + 31) / 32, 256>>>(x, act, W0, b0, ln0g, ln0b);
    k_hist   <<<(EP + 255) / 256, 256>>>(ei);
    k_gemm_gat<<<GEMM_GRID, 256, 57344>>>(Wg, asrc, adst);   // layer 0 linear
    k_scan   <<<1, 1024>>>();
    k_scatter<<<(EP + 255) / 256, 256>>>(ei);

    // 3 GAT layers (layer-0 GEMM already issued)
    for (int l = 0; l < 3; l++) {
        if (l > 0)
            k_gemm_gat<<<GEMM_GRID, 256, 57344>>>(
                Wg + (size_t)l * HDIM * HDIM, asrc + l * HDIM, adst + l * HDIM);
        k_attn<<<NN / 8, 256>>>(bg + l * HDIM, lngg + l * HDIM, lngb + l * HDIM);
    }

    // dynamics head (writes delta_x and next_x; also accumulates mean-pool)
    k_dyn<<<(NN + 31) / 32, 256, 98304>>>(x, Wd1, bd1, Wd2, bd2, out);

    // pooled heads
    k_heads<<<1, 128>>>(Wr1, br1, Wr2, br2, Wc1, bc1, Wc2, bc2, out);
}

// round 17
// speedup vs baseline: 1.0362x; 1.0362x over previous
#include <cuda_runtime.h>

#define NN   50000
#define EE   600000
#define EP   650000      // EE + NN self loops
#define FEAT 32
#define ACTD 8
#define HDIM 128
#define NEG  0.2f
#define LEPS 1e-5f
#define GROWS 48         // rows per k_gemm_gat block

typedef unsigned long long u64t;

// ---------------- device scratch (no allocations allowed) ----------------
__device__ float g_h    [NN * HDIM];
__device__ float g_xp   [NN * HDIM];
__device__ float g_ssrc [NN * 4];
__device__ float g_sdst [NN * 4];
__device__ int   g_cnt  [NN];
__device__ int   g_off  [NN + 1];
__device__ int   g_cur  [NN];
__device__ int   g_srcs [EP];
__device__ float g_gsum [HDIM];

__device__ __forceinline__ float lrelu(float a) { return a > 0.f ? a : NEG * a; }
__device__ __forceinline__ float wredsum(float v) {
    #pragma unroll
    for (int o = 16; o > 0; o >>= 1) v += __shfl_xor_sync(0xffffffffu, v, o);
    return v;
}
__device__ __forceinline__ u64t fma2(u64t a, u64t b, u64t c) {
    u64t d;
    asm("fma.rn.f32x2 %0, %1, %2, %3;" : "=l"(d) : "l"(a), "l"(b), "l"(c));
    return d;
}
__device__ __forceinline__ float2 unpk(u64t v) {
    float2 r;
    asm("mov.b64 {%0, %1}, %2;" : "=f"(r.x), "=f"(r.y) : "l"(v));
    return r;
}

// ---------------- CSR build ----------------
__global__ void k_zero() {
    int i = blockIdx.x * blockDim.x + threadIdx.x;
    if (i < NN)   g_cnt[i]  = 0;
    if (i < HDIM) g_gsum[i] = 0.f;
}

__global__ void k_hist(const int* __restrict__ ei) {
    int e = blockIdx.x * blockDim.x + threadIdx.x;
    if (e >= EP) return;
    int d = (e < EE) ? ei[EE + e] : (e - EE);
    atomicAdd(&g_cnt[d], 1);
}

__global__ void k_scan() {
    __shared__ int ps[1024];
    int t = threadIdx.x;
    const int CH = (NN + 1023) / 1024;     // 49
    int s0 = t * CH;
    int s1 = min(s0 + CH, NN);
    int s = 0;
    for (int i = s0; i < s1; i++) s += g_cnt[i];
    ps[t] = s;
    __syncthreads();
    #pragma unroll
    for (int d = 1; d < 1024; d <<= 1) {
        int add = (t >= d) ? ps[t - d] : 0;
        __syncthreads();
        ps[t] += add;
        __syncthreads();
    }
    int run = t ? ps[t - 1] : 0;
    for (int i = s0; i < s1; i++) {
        g_off[i] = run;
        g_cur[i] = run;
        run += g_cnt[i];
    }
    if (t == 1023) g_off[NN] = ps[1023];
}

__global__ void k_scatter(const int* __restrict__ ei) {
    int e = blockIdx.x * blockDim.x + threadIdx.x;
    if (e >= EP) return;
    int s, d;
    if (e < EE) { s = ei[e]; d = ei[EE + e]; }
    else        { s = e - EE; d = s; }
    int p = atomicAdd(&g_cur[d], 1);
    g_srcs[p] = s;
}

// ---------------- encoder (f32x2): h = relu(LN(concat(x,act) @ W0 + b0)) --------------
__global__ void __launch_bounds__(256) k_enc(
    const float* __restrict__ x, const float* __restrict__ act,
    const float* __restrict__ W0, const float* __restrict__ b0,
    const float* __restrict__ lg, const float* __restrict__ lb)
{
    __shared__ float Wsm[20 * 256];   // k-pair interleaved: (k,c) -> (k/2)*256 + c*2 + (k&1)
    __shared__ float Rsm[32 * 40];
    int tid = threadIdx.x;
    for (int i = tid; i < 40 * HDIM; i += 256) {
        int k = i >> 7, c = i & 127;
        Wsm[(k >> 1) * 256 + c * 2 + (k & 1)] = W0[i];
    }
    int row0 = blockIdx.x * 32;
    for (int i = tid; i < 32 * 40; i += 256) {
        int r = i / 40, c = i - r * 40;
        int row = row0 + r;
        float v = 0.f;
        if (row < NN) v = (c < FEAT) ? x[row * FEAT + c] : act[row * ACTD + (c - FEAT)];
        Rsm[i] = v;
    }
    __syncthreads();
    int l = tid & 31, w4 = (tid >> 5) * 4;
    u64t acc[4][4] = {};
    #pragma unroll 4
    for (int kk = 0; kk < 20; kk++) {
        const u64t* wrow = (const u64t*)(Wsm + kk * 256);
        u64t w0 = wrow[l], w1 = wrow[l + 32], w2 = wrow[l + 64], w3 = wrow[l + 96];
        #pragma unroll
        for (int i = 0; i < 4; i++) {
            u64t h = *(const u64t*)(Rsm + (w4 + i) * 40 + kk * 2);
            acc[i][0] = fma2(h, w0, acc[i][0]);
            acc[i][1] = fma2(h, w1, acc[i][1]);
            acc[i][2] = fma2(h, w2, acc[i][2]);
            acc[i][3] = fma2(h, w3, acc[i][3]);
        }
    }
    float bb0 = b0[l], bb1 = b0[l + 32], bb2 = b0[l + 64], bb3 = b0[l + 96];
    float gg0 = lg[l], gg1 = lg[l + 32], gg2 = lg[l + 64], gg3 = lg[l + 96];
    float be0 = lb[l], be1 = lb[l + 32], be2 = lb[l + 64], be3 = lb[l + 96];
    #pragma unroll
    for (int i = 0; i < 4; i++) {
        int row = row0 + w4 + i;
        float2 p0 = unpk(acc[i][0]), p1 = unpk(acc[i][1]);
        float2 p2 = unpk(acc[i][2]), p3 = unpk(acc[i][3]);
        float v0 = p0.x + p0.y + bb0, v1 = p1.x + p1.y + bb1;
        float v2 = p2.x + p2.y + bb2, v3 = p3.x + p3.y + bb3;
        float sum = wredsum(v0 + v1 + v2 + v3);
        float sq  = wredsum(v0 * v0 + v1 * v1 + v2 * v2 + v3 * v3);
        float mu  = sum * (1.f / HDIM);
        float var = sq * (1.f / HDIM) - mu * mu;
        float rs  = rsqrtf(var + LEPS);
        if (row < NN) {
            int o = row * HDIM + l;
            g_h[o]      = fmaxf((v0 - mu) * rs * gg0 + be0, 0.f);
            g_h[o + 32] = fmaxf((v1 - mu) * rs * gg1 + be1, 0.f);
            g_h[o + 64] = fmaxf((v2 - mu) * rs * gg2 + be2, 0.f);
            g_h[o + 96] = fmaxf((v3 - mu) * rs * gg3 + be3, 0.f);
        }
    }
}

// ---------------- GAT linear (f32x2, split-N): 48 rows x 64 cols per block ------------
// 56KB smem/block -> 4 blocks/SM. Col-half 0 = heads 0,1; col-half 1 = heads 2,3,
// so per-head attention-score reductions stay warp-local. (R12-proven config.)
__global__ void __launch_bounds__(256) k_gemm_gat(
    const float* __restrict__ W,
    const float* __restrict__ asrc, const float* __restrict__ adst)
{
    extern __shared__ float sm[];
    float* Wsm = sm;                    // 64 kk-rows * 128 floats = 32KB (k-pair interleaved)
    float* Hsm = sm + 64 * 128;         // GROWS * 128 = 24KB
    int tid = threadIdx.x;
    int bx = blockIdx.x >> 1, chalf = blockIdx.x & 1;
    int c0 = chalf * 64;
    // repack W cols [c0, c0+64): (k, c) -> Wsm[(k/2)*128 + (c-c0)*2 + (k&1)]
    for (int i = tid; i < HDIM * 64; i += 256) {
        int k = i >> 6, cc = i & 63;
        Wsm[(k >> 1) * 128 + cc * 2 + (k & 1)] = W[k * HDIM + c0 + cc];
    }
    int row0 = bx * GROWS;
    for (int i = tid; i < GROWS * HDIM; i += 256) {
        int r = i >> 7, c = i & 127;
        int row = row0 + r;
        Hsm[i] = (row < NN) ? g_h[row * HDIM + c] : 0.f;
    }
    __syncthreads();
    int l = tid & 31, w6 = (tid >> 5) * 6;
    u64t acc[6][2] = {};
    #pragma unroll 4
    for (int kk = 0; kk < 64; kk++) {
        const u64t* wrow = (const u64t*)(Wsm + kk * 128);
        u64t w0 = wrow[l], w1 = wrow[l + 32];
        #pragma unroll
        for (int i = 0; i < 6; i++) {
            u64t h = *(const u64t*)(Hsm + (w6 + i) * HDIM + kk * 2);
            acc[i][0] = fma2(h, w0, acc[i][0]);
            acc[i][1] = fma2(h, w1, acc[i][1]);
        }
    }
    float as0 = asrc[c0 + l], as1 = asrc[c0 + 32 + l];
    float ad0 = adst[c0 + l], ad1 = adst[c0 + 32 + l];
    #pragma unroll
    for (int i = 0; i < 6; i++) {
        int row = row0 + w6 + i;
        float2 u0 = unpk(acc[i][0]), u1 = unpk(acc[i][1]);
        float v0 = u0.x + u0.y, v1 = u1.x + u1.y;
        float p0 = wredsum(v0 * as0);   // head chalf*2 + 0
        float p1 = wredsum(v1 * as1);   // head chalf*2 + 1
        float q0 = wredsum(v0 * ad0);
        float q1 = wredsum(v1 * ad1);
        if (row < NN) {
            if (l == 0) {
                g_ssrc[row * 4 + chalf * 2 + 0] = p0;
                g_ssrc[row * 4 + chalf * 2 + 1] = p1;
                g_sdst[row * 4 + chalf * 2 + 0] = q0;
                g_sdst[row * 4 + chalf * 2 + 1] = q1;
            }
            int o = row * HDIM + c0 + l;
            g_xp[o]      = v0;
            g_xp[o + 32] = v1;
        }
    }
}

// ---------------- single-pass attention + aggregate + LN + relu + residual ------------
__global__ void __launch_bounds__(256) k_attn(
    const float* __restrict__ bias,
    const float* __restrict__ lg, const float* __restrict__ lb)
{
    __shared__ float sw[8][128];
    int warp = threadIdx.x >> 5, lane = threadIdx.x & 31;
    int node = blockIdx.x * 8 + warp;      // grid = NN/8 exactly
    int beg = g_off[node], end = g_off[node + 1];
    const float4 sd = *(const float4*)(g_sdst + node * 4);

    int head = lane >> 3;
    int colb = lane * 4;
    float den0 = 0.f, den1 = 0.f, den2 = 0.f, den3 = 0.f;
    float4 acc = make_float4(0.f, 0.f, 0.f, 0.f);

    for (int base = beg; base < end; base += 32) {
        int e = base + lane;
        int s = 0;
        float a0 = 0.f, a1 = 0.f, a2 = 0.f, a3 = 0.f;
        if (e < end) {
            s = g_srcs[e];
            float4 sv = *(const float4*)(g_ssrc + s * 4);
            a0 = __expf(lrelu(sv.x + sd.x));
            a1 = __expf(lrelu(sv.y + sd.y));
            a2 = __expf(lrelu(sv.z + sd.z));
            a3 = __expf(lrelu(sv.w + sd.w));
        }
        den0 += a0; den1 += a1; den2 += a2; den3 += a3;
        __syncwarp();
        float* swp = sw[warp] + lane * 4;
        swp[0] = a0; swp[1] = a1; swp[2] = a2; swp[3] = a3;
        __syncwarp();
        int cnt4 = (min(32, end - base) + 3) & ~3;
        for (int j = 0; j < cnt4; j += 4) {
            int   sj[4];
            float wv[4];
            #pragma unroll
            for (int u = 0; u < 4; u++) {
                sj[u] = __shfl_sync(0xffffffffu, s, j + u);
                wv[u] = sw[warp][(j + u) * 4 + head];
            }
            #pragma unroll
            for (int u = 0; u < 4; u++) {
                float4 xv = *(const float4*)(g_xp + (size_t)sj[u] * HDIM + colb);
                acc.x = fmaf(wv[u], xv.x, acc.x);
                acc.y = fmaf(wv[u], xv.y, acc.y);
                acc.z = fmaf(wv[u], xv.z, acc.z);
                acc.w = fmaf(wv[u], xv.w, acc.w);
            }
        }
    }

    den0 = wredsum(den0); den1 = wredsum(den1);
    den2 = wredsum(den2); den3 = wredsum(den3);
    float dh = (head == 0) ? den0 : (head == 1) ? den1 : (head == 2) ? den2 : den3;
    float inv = 1.f / dh;
    acc.x *= inv; acc.y *= inv; acc.z *= inv; acc.w *= inv;

    // bias + LayerNorm + relu + residual, fully in-warp
    float4 bb = *(const float4*)(bias + colb);
    acc.x += bb.x; acc.y += bb.y; acc.z += bb.z; acc.w += bb.w;
    float sum = wredsum(acc.x + acc.y + acc.z + acc.w);
    float sq  = wredsum(acc.x * acc.x + acc.y * acc.y + acc.z * acc.z + acc.w * acc.w);
    float mu  = sum * (1.f / 128.f);
    float var = sq * (1.f / 128.f) - mu * mu;
    float rs  = rsqrtf(var + LEPS);
    float4 gg = *(const float4*)(lg + colb);
    float4 be = *(const float4*)(lb + colb);
    float4 hv = *(float4*)(g_h + (size_t)node * HDIM + colb);
    hv.x += fmaxf((acc.x - mu) * rs * gg.x + be.x, 0.f);
    hv.y += fmaxf((acc.y - mu) * rs * gg.y + be.y, 0.f);
    hv.z += fmaxf((acc.z - mu) * rs * gg.z + be.z, 0.f);
    hv.w += fmaxf((acc.w - mu) * rs * gg.w + be.w, 0.f);
    *(float4*)(g_h + (size_t)node * HDIM + colb) = hv;
}

// ---------------- dynamics head (f32x2) + fused mean-pool partials ----------------
__global__ void __launch_bounds__(256) k_dyn(
    const float* __restrict__ x,
    const float* __restrict__ W1, const float* __restrict__ b1,
    const float* __restrict__ W2, const float* __restrict__ b2,
    float* __restrict__ out)
{
    extern __shared__ float sm[];
    float* W1sm = sm;            // 16384 (k-pair interleaved)
    float* W2sm = sm + 16384;    // 4096  (k-pair interleaved)
    float* Rsm  = sm + 20480;    // 32*128
    int tid = threadIdx.x;
    for (int i = tid; i < HDIM * HDIM; i += 256) {
        int k = i >> 7, c = i & 127;
        W1sm[(k >> 1) * 256 + c * 2 + (k & 1)] = W1[i];
    }
    for (int i = tid; i < HDIM * FEAT; i += 256) {
        int k = i >> 5, c = i & 31;
        W2sm[(k >> 1) * 64 + c * 2 + (k & 1)] = W2[i];
    }
    int row0 = blockIdx.x * 32;
    for (int i = tid; i < 32 * HDIM; i += 256) {
        int r = i >> 7, c = i & 127;
        int row = row0 + r;
        Rsm[i] = (row < NN) ? g_h[row * HDIM + c] : 0.f;
    }
    __syncthreads();

    // fused global mean-pool partial (h tile already in smem; zeros past NN harmless)
    {
        int col = tid & 127, rh = tid >> 7;
        float s = 0.f;
        #pragma unroll
        for (int r = rh * 16; r < rh * 16 + 16; r++) s += Rsm[r * HDIM + col];
        atomicAdd(&g_gsum[col], s);
    }

    int l = tid & 31, w4 = (tid >> 5) * 4;
    u64t acc[4][4] = {};
    #pragma unroll 4
    for (int kk = 0; kk < 64; kk++) {
        const u64t* wrow = (const u64t*)(W1sm + kk * 256);
        u64t w0 = wrow[l], w1 = wrow[l + 32], w2 = wrow[l + 64], w3 = wrow[l + 96];
        #pragma unroll
        for (int i = 0; i < 4; i++) {
            u64t h = *(const u64t*)(Rsm + (w4 + i) * HDIM + kk * 2);
            acc[i][0] = fma2(h, w0, acc[i][0]);
            acc[i][1] = fma2(h, w1, acc[i][1]);
            acc[i][2] = fma2(h, w2, acc[i][2]);
            acc[i][3] = fma2(h, w3, acc[i][3]);
        }
    }
    float bb0 = b1[l], bb1 = b1[l + 32], bb2 = b1[l + 64], bb3 = b1[l + 96];
    __syncthreads();
    #pragma unroll
    for (int i = 0; i < 4; i++) {
        int ro = (w4 + i) * HDIM;
        float2 p0 = unpk(acc[i][0]), p1 = unpk(acc[i][1]);
        float2 p2 = unpk(acc[i][2]), p3 = unpk(acc[i][3]);
        Rsm[ro + l]      = fmaxf(p0.x + p0.y + bb0, 0.f);
        Rsm[ro + l + 32] = fmaxf(p1.x + p1.y + bb1, 0.f);
        Rsm[ro + l + 64] = fmaxf(p2.x + p2.y + bb2, 0.f);
        Rsm[ro + l + 96] = fmaxf(p3.x + p3.y + bb3, 0.f);
    }
    __syncthreads();
    u64t dacc[4] = {};
    #pragma unroll 4
    for (int kk = 0; kk < 64; kk++) {
        u64t w = *(const u64t*)(W2sm + kk * 64 + l * 2);
        #pragma unroll
        for (int i = 0; i < 4; i++) {
            u64t h = *(const u64t*)(Rsm + (w4 + i) * HDIM + kk * 2);
            dacc[i] = fma2(h, w, dacc[i]);
        }
    }
    float bv = b2[l];
    #pragma unroll
    for (int i = 0; i < 4; i++) {
        int row = row0 + w4 + i;
        if (row < NN) {
            float2 p = unpk(dacc[i]);
            float dv = p.x + p.y + bv;
            out[row * FEAT + l] = dv;
            out[NN * FEAT + row * FEAT + l] = x[row * FEAT + l] + dv;
        }
    }
}

// ---------------- reward/constraint heads ----------------
__global__ void k_heads(
    const float* __restrict__ Wr1, const float* __restrict__ br1,
    const float* __restrict__ Wr2, const float* __restrict__ br2,
    const float* __restrict__ Wc1, const float* __restrict__ bc1,
    const float* __restrict__ Wc2, const float* __restrict__ bc2,
    float* __restrict__ out)
{
    __shared__ float emb[128];
    __shared__ float t1[64];
    __shared__ float t2[64];
    int t = threadIdx.x;   // 128
    emb[t] = g_gsum[t] * (1.f / NN);
    __syncthreads();
    if (t < 64) {
        float a = br1[t], c = bc1[t];
        #pragma unroll 4
        for (int k = 0; k < 128; k++) {
            a = fmaf(emb[k], Wr1[k * 64 + t], a);
            c = fmaf(emb[k], Wc1[k * 64 + t], c);
        }
        t1[t] = fmaxf(a, 0.f);
        t2[t] = fmaxf(c, 0.f);
    }
    __syncthreads();
    if (t == 0) {
        float r = br2[0], c = bc2[0];
        for (int k = 0; k < 64; k++) {
            r = fmaf(t1[k], Wr2[k], r);
            c = fmaf(t2[k], Wc2[k], c);
        }
        out[2 * NN * FEAT]     = r;
        out[2 * NN * FEAT + 1] = 1.f / (1.f + expf(-c));
    }
}

// ---------------- launch (single stream — graph-capture safe) ----------------
extern "C" void kernel_launch(void* const* d_in, const int* in_sizes, int n_in,
                              void* d_out, int out_size)
{
    const float* x    = (const float*)d_in[0];
    const float* act  = (const float*)d_in[1];
    const int*   ei   = (const int*)  d_in[2];
    const float* W0   = (const float*)d_in[3];
    const float* b0   = (const float*)d_in[4];
    const float* ln0g = (const float*)d_in[5];
    const float* ln0b = (const float*)d_in[6];
    const float* Wg   = (const float*)d_in[7];
    const float* asrc = (const float*)d_in[8];
    const float* adst = (const float*)d_in[9];
    const float* bg   = (const float*)d_in[10];
    const float* lngg = (const float*)d_in[11];
    const float* lngb = (const float*)d_in[12];
    const float* Wd1  = (const float*)d_in[13];
    const float* bd1  = (const float*)d_in[14];
    const float* Wd2  = (const float*)d_in[15];
    const float* bd2  = (const float*)d_in[16];
    const float* Wr1  = (const float*)d_in[17];
    const float* br1  = (const float*)d_in[18];
    const float* Wr2  = (const float*)d_in[19];
    const float* br2  = (const float*)d_in[20];
    const float* Wc1  = (const float*)d_in[21];
    const float* bc1  = (const float*)d_in[22];
    const float* Wc2  = (const float*)d_in[23];
    const float* bc2  = (const float*)d_in[24];
    float* out = (float*)d_out;

    cudaFuncSetAttribute(k_gemm_gat, cudaFuncAttributeMaxDynamicSharedMemorySize, 57344);
    cudaFuncSetAttribute(k_dyn,      cudaFuncAttributeMaxDynamicSharedMemorySize, 98304);

    const int GEMM_GRID = ((NN + GROWS - 1) / GROWS) * 2;   // split-N: 2 col-halves

    // Interleave CSR build with encoder/layer-0 GEMM (sequentially correct on one
    // stream; keeps k_gemm_gat in the ncu capture slot for visibility).
    k_zero   <<<(NN + 255) / 256, 256>>>();
    k_enc    <<<(NN + 31) / 32, 256>>>(x, act, W0, b0, ln0g, ln0b);
    k_hist   <<<(EP + 255) / 256, 256>>>(ei);
    k_gemm_gat<<<GEMM_GRID, 256, 57344>>>(Wg, asrc, adst);   // layer 0 linear
    k_scan   <<<1, 1024>>>();
    k_scatter<<<(EP + 255) / 256, 256>>>(ei);

    // 3 GAT layers (layer-0 GEMM already issued)
    for (int l = 0; l < 3; l++) {
        if (l > 0)
            k_gemm_gat<<<GEMM_GRID, 256, 57344>>>(
                Wg + (size_t)l * HDIM * HDIM, asrc + l * HDIM, adst + l * HDIM);
        k_attn<<<NN / 8, 256>>>(bg + l * HDIM, lngg + l * HDIM, lngb + l * HDIM);
    }

    // dynamics head (writes delta_x and next_x; also accumulates mean-pool)
    k_dyn<<<(NN + 31) / 32, 256, 98304>>>(x, Wd1, bd1, Wd2, bd2, out);

    // pooled heads
    k_heads<<<1, 128>>>(Wr1, br1, Wr2, br2, Wc1, bc1, Wc2, bc2, out);
}